// round 6
// baseline (speedup 1.0000x reference)
#include <cuda_runtime.h>
#include <cuda_fp16.h>
#include <cuda_bf16.h>
#include <cstring>
#include <cstdint>

#define DIM 128
#define MAX_NODES 100000
#define MAX_EDGES 1600000
#define SCAN_BLK 1024
#define MAX_SCAN_BLOCKS 128
#define PADK 136   // padded k-stride (elements): 272B row stride -> ldmatrix conflict-free

// Static device scratch (no allocs allowed).
__device__ __half g_support[MAX_NODES * DIM];           // 25.6 MB, L2-resident
__device__ int g_count[MAX_NODES];
__device__ int g_offset[MAX_NODES];
__device__ int g_cursor[MAX_NODES];
__device__ int g_blocksums[MAX_SCAN_BLOCKS];
__device__ unsigned long long g_bins[MAX_EDGES];        // (val<<32)|src, 12.8 MB
// Pre-split, pre-transposed weights: g_W*[n][k] (bf16).
__device__ __nv_bfloat16 g_Whi[DIM * DIM];
__device__ __nv_bfloat16 g_Wlo[DIM * DIM];

__device__ __forceinline__ uint32_t smem_u32(const void* p) {
    uint32_t a;
    asm("{ .reg .u64 t; cvta.to.shared.u64 t, %1; cvt.u32.u64 %0, t; }"
        : "=r"(a) : "l"(p));
    return a;
}
__device__ __forceinline__ unsigned int pack_half2f(float a, float b) {
    __half2 h = __floats2half2_rn(a, b);
    unsigned int u;
    memcpy(&u, &h, 4);
    return u;
}
__device__ __forceinline__ void ldsm_x4(uint32_t& r0, uint32_t& r1,
                                        uint32_t& r2, uint32_t& r3, uint32_t addr) {
    asm volatile("ldmatrix.sync.aligned.m8n8.x4.shared.b16 {%0,%1,%2,%3}, [%4];"
                 : "=r"(r0), "=r"(r1), "=r"(r2), "=r"(r3) : "r"(addr));
}
__device__ __forceinline__ void mma_bf16(float* c, const uint32_t* a,
                                         uint32_t b0, uint32_t b1) {
    asm volatile("mma.sync.aligned.m16n8k16.row.col.f32.bf16.bf16.f32 "
                 "{%0,%1,%2,%3}, {%4,%5,%6,%7}, {%8,%9}, {%0,%1,%2,%3};"
                 : "+f"(c[0]), "+f"(c[1]), "+f"(c[2]), "+f"(c[3])
                 : "r"(a[0]), "r"(a[1]), "r"(a[2]), "r"(a[3]), "r"(b0), "r"(b1));
}

// ---------------------------------------------------------------------------
// W split/transpose pre-pass: g_W{hi,lo}[n][k] = bf16 hi/lo split of W[k][n].
// ---------------------------------------------------------------------------
__global__ void wsplit_kernel(const float* __restrict__ W) {
    int i = blockIdx.x * blockDim.x + threadIdx.x;
    if (i < DIM * DIM) {
        int k = i >> 7, n = i & 127;
        float w = W[i];
        __nv_bfloat16 h = __float2bfloat16(w);
        float lo = w - __bfloat162float(h);
        g_Whi[n * DIM + k] = h;
        g_Wlo[n * DIM + k] = __float2bfloat16(lo);
    }
}

// ---------------------------------------------------------------------------
// Tensor-core GEMM via mma.sync (bf16 hi/lo split, fp32 accum, fp16 store).
// Block: 256 thr (8 warps) computes 128 rows x 128 cols.
// Warp grid 4(M) x 2(N): warp tile 32 rows x 64 cols.
// smem: Ahi/Alo/Whi/Wlo, each 128 x PADK bf16 (34816B) -> 139264B total.
// ---------------------------------------------------------------------------
__global__ void __launch_bounds__(256) gemm_mma_kernel(const float* __restrict__ X,
                                                       int n_rows) {
    extern __shared__ char dsm[];
    __nv_bfloat16* sAhi = reinterpret_cast<__nv_bfloat16*>(dsm);
    __nv_bfloat16* sAlo = sAhi + 128 * PADK;
    __nv_bfloat16* sWhi = sAlo + 128 * PADK;
    __nv_bfloat16* sWlo = sWhi + 128 * PADK;

    int tid = threadIdx.x;
    int warp = tid >> 5;
    int lane = tid & 31;
    int row0 = blockIdx.x * 128;

    // Copy pre-split W [n][k] into padded smem (uint4 = 8 bf16).
    for (int i = tid; i < 128 * 16; i += 256) {
        int n = i >> 4;
        int kc = i & 15;
        *reinterpret_cast<uint4*>(sWhi + n * PADK + kc * 8) =
            *reinterpret_cast<const uint4*>(g_Whi + n * DIM + kc * 8);
        *reinterpret_cast<uint4*>(sWlo + n * PADK + kc * 8) =
            *reinterpret_cast<const uint4*>(g_Wlo + n * DIM + kc * 8);
    }

    // Load X tile, split to bf16 hi/lo, store padded smem (uint2 = 4 bf16).
    for (int i = tid; i < 128 * 32; i += 256) {
        int r = i >> 5;
        int k4 = i & 31;
        float4 v = make_float4(0.f, 0.f, 0.f, 0.f);
        if (row0 + r < n_rows)
            v = *reinterpret_cast<const float4*>(X + (size_t)(row0 + r) * DIM + k4 * 4);
        const float* vp = reinterpret_cast<const float*>(&v);
        __nv_bfloat16 h[4], l[4];
#pragma unroll
        for (int j = 0; j < 4; j++) {
            h[j] = __float2bfloat16(vp[j]);
            l[j] = __float2bfloat16(vp[j] - __bfloat162float(h[j]));
        }
        uint2 ph, pl;
        memcpy(&ph, h, 8);
        memcpy(&pl, l, 8);
        *reinterpret_cast<uint2*>(sAhi + r * PADK + k4 * 4) = ph;
        *reinterpret_cast<uint2*>(sAlo + r * PADK + k4 * 4) = pl;
    }
    __syncthreads();

    int wm = warp & 3;            // 0..3 -> M offset
    int wn = warp >> 2;           // 0..1 -> N offset
    int mrow = wm * 32;
    int ncol = wn * 64;

    float acc[2][8][4];
#pragma unroll
    for (int mt = 0; mt < 2; mt++)
#pragma unroll
        for (int nt = 0; nt < 8; nt++)
#pragma unroll
            for (int q = 0; q < 4; q++) acc[mt][nt][q] = 0.f;

    uint32_t aBaseHi = smem_u32(sAhi);
    uint32_t aBaseLo = smem_u32(sAlo);
    uint32_t wBaseHi = smem_u32(sWhi);
    uint32_t wBaseLo = smem_u32(sWlo);

    // A ldmatrix lane address pattern: row = base + (lane&15), k = k0 + ((lane>>4)<<3)
    int a_r = lane & 15;
    int a_k = (lane >> 4) << 3;
    // B ldmatrix (2 n-tiles per x4): n = base + ((lane>>4)<<3) + (lane&7),
    //                                k = k0 + (((lane>>3)&1)<<3)
    int b_n = ((lane >> 4) << 3) + (lane & 7);
    int b_k = ((lane >> 3) & 1) << 3;

#pragma unroll
    for (int ks = 0; ks < 8; ks++) {
        int k0 = ks * 16;

        uint32_t ahi[2][4], alo[2][4];
#pragma unroll
        for (int mt = 0; mt < 2; mt++) {
            uint32_t off = (uint32_t)(((mrow + mt * 16 + a_r) * PADK + k0 + a_k) * 2);
            ldsm_x4(ahi[mt][0], ahi[mt][1], ahi[mt][2], ahi[mt][3], aBaseHi + off);
            ldsm_x4(alo[mt][0], alo[mt][1], alo[mt][2], alo[mt][3], aBaseLo + off);
        }

#pragma unroll
        for (int bp = 0; bp < 4; bp++) {          // pairs of n-tiles
            uint32_t off = (uint32_t)(((ncol + bp * 16 + b_n) * PADK + k0 + b_k) * 2);
            uint32_t h0, h1, h2, h3, l0, l1, l2, l3;
            ldsm_x4(h0, h1, h2, h3, wBaseHi + off);
            ldsm_x4(l0, l1, l2, l3, wBaseLo + off);
            int nt0 = bp * 2, nt1 = bp * 2 + 1;
#pragma unroll
            for (int mt = 0; mt < 2; mt++) {
                mma_bf16(acc[mt][nt0], ahi[mt], h0, h1);
                mma_bf16(acc[mt][nt0], ahi[mt], l0, l1);
                mma_bf16(acc[mt][nt0], alo[mt], h0, h1);
                mma_bf16(acc[mt][nt1], ahi[mt], h2, h3);
                mma_bf16(acc[mt][nt1], ahi[mt], l2, l3);
                mma_bf16(acc[mt][nt1], alo[mt], h2, h3);
            }
        }
    }

    // Epilogue: c-frag (row = lane>>2 [+8], col = (lane&3)*2) -> fp16 g_support.
#pragma unroll
    for (int mt = 0; mt < 2; mt++) {
        int r0g = row0 + mrow + mt * 16 + (lane >> 2);
        int r1g = r0g + 8;
#pragma unroll
        for (int nt = 0; nt < 8; nt++) {
            int col = ncol + nt * 8 + (lane & 3) * 2;
            if (r0g < n_rows)
                *reinterpret_cast<unsigned int*>(g_support + (size_t)r0g * DIM + col) =
                    pack_half2f(acc[mt][nt][0], acc[mt][nt][1]);
            if (r1g < n_rows)
                *reinterpret_cast<unsigned int*>(g_support + (size_t)r1g * DIM + col) =
                    pack_half2f(acc[mt][nt][2], acc[mt][nt][3]);
        }
    }
}

// ---------------------------------------------------------------------------
// CSR binning: zero counts -> histogram -> 3-phase exclusive scan -> fill.
// ---------------------------------------------------------------------------
__global__ void zero_counts_kernel(int n_nodes) {
    int i = blockIdx.x * blockDim.x + threadIdx.x;
    if (i < n_nodes) g_count[i] = 0;
}

__global__ void hist_kernel(const int* __restrict__ dst, int n_edges) {
    int i = blockIdx.x * blockDim.x + threadIdx.x;
    int stride = gridDim.x * blockDim.x;
    for (; i < n_edges; i += stride)
        atomicAdd(&g_count[dst[i]], 1);
}

__global__ void __launch_bounds__(256) scan1_kernel(int n_nodes) {
    __shared__ int s[256];
    int base = blockIdx.x * SCAN_BLK;
    int t = threadIdx.x;
    int v[4];
    int sum = 0;
#pragma unroll
    for (int j = 0; j < 4; j++) {
        int idx = base + t * 4 + j;
        v[j] = (idx < n_nodes) ? g_count[idx] : 0;
        sum += v[j];
    }
    s[t] = sum;
    __syncthreads();
    for (int off = 1; off < 256; off <<= 1) {
        int x = (t >= off) ? s[t - off] : 0;
        __syncthreads();
        s[t] += x;
        __syncthreads();
    }
    int excl = s[t] - sum;
    if (t == 255) g_blocksums[blockIdx.x] = s[255];
    int run = excl;
#pragma unroll
    for (int j = 0; j < 4; j++) {
        int idx = base + t * 4 + j;
        if (idx < n_nodes) g_offset[idx] = run;
        run += v[j];
    }
}

__global__ void __launch_bounds__(128) scan2_kernel(int nb) {
    __shared__ int s[128];
    int t = threadIdx.x;
    int v = (t < nb) ? g_blocksums[t] : 0;
    s[t] = v;
    __syncthreads();
    for (int off = 1; off < 128; off <<= 1) {
        int x = (t >= off) ? s[t - off] : 0;
        __syncthreads();
        s[t] += x;
        __syncthreads();
    }
    if (t < nb) g_blocksums[t] = s[t] - v;
}

__global__ void scan3_kernel(int n_nodes) {
    int i = blockIdx.x * blockDim.x + threadIdx.x;
    if (i < n_nodes) {
        int o = g_offset[i] + g_blocksums[i / SCAN_BLK];
        g_offset[i] = o;
        g_cursor[i] = o;
    }
}

__global__ void fill_kernel(const float* __restrict__ vals,
                            const int* __restrict__ src,
                            const int* __restrict__ dst,
                            int n_edges) {
    int i = blockIdx.x * blockDim.x + threadIdx.x;
    if (i < n_edges) {
        int d = dst[i];
        int pos = atomicAdd(&g_cursor[d], 1);
        g_bins[pos] = ((unsigned long long)__float_as_uint(vals[i]) << 32) |
                      (unsigned int)src[i];
    }
}

// ---------------------------------------------------------------------------
// Gather: one warp per dst node, 4-edge pipeline, fused ReLU, single write.
// ---------------------------------------------------------------------------
__global__ void __launch_bounds__(256) gather_kernel(float* __restrict__ out,
                                                     int n_nodes) {
    int warp = (blockIdx.x * blockDim.x + threadIdx.x) >> 5;
    int lane = threadIdx.x & 31;
    if (warp >= n_nodes) return;

    int o0 = g_offset[warp];
    int deg = g_count[warp];

    float4 acc = make_float4(0.f, 0.f, 0.f, 0.f);

    for (int e = 0; e < deg; e += 4) {
        unsigned long long p[4];
#pragma unroll
        for (int j = 0; j < 4; j++)
            p[j] = (e + j < deg) ? __ldg(g_bins + o0 + e + j) : 0ull;

        uint2 hv[4];
#pragma unroll
        for (int j = 0; j < 4; j++) {
            int s = (int)(p[j] & 0xffffffffull);
            hv[j] = __ldg(reinterpret_cast<const uint2*>(
                g_support + (size_t)s * DIM + lane * 4));
        }
#pragma unroll
        for (int j = 0; j < 4; j++) {
            float v = __uint_as_float((unsigned int)(p[j] >> 32));
            __half2 a, b;
            memcpy(&a, &hv[j].x, 4);
            memcpy(&b, &hv[j].y, 4);
            float2 fa = __half22float2(a);
            float2 fb = __half22float2(b);
            acc.x = fmaf(v, fa.x, acc.x);
            acc.y = fmaf(v, fa.y, acc.y);
            acc.z = fmaf(v, fb.x, acc.z);
            acc.w = fmaf(v, fb.y, acc.w);
        }
    }

    acc.x = fmaxf(acc.x, 0.f);
    acc.y = fmaxf(acc.y, 0.f);
    acc.z = fmaxf(acc.z, 0.f);
    acc.w = fmaxf(acc.w, 0.f);
    *reinterpret_cast<float4*>(out + (size_t)warp * DIM + lane * 4) = acc;
}

extern "C" void kernel_launch(void* const* d_in, const int* in_sizes, int n_in,
                              void* d_out, int out_size) {
    const float* X    = (const float*)d_in[0];   // [n_nodes, 128]
    const float* W    = (const float*)d_in[1];   // [128, 128]
    const float* vals = (const float*)d_in[2];   // [E]
    const int*   src  = (const int*)d_in[3];     // [E]
    const int*   dst  = (const int*)d_in[4];     // [E]
    float* out = (float*)d_out;

    int n_nodes = in_sizes[0] / DIM;
    int n_edges = in_sizes[2];
    int nb = (n_nodes + SCAN_BLK - 1) / SCAN_BLK;

    // Binning pipeline front half.
    zero_counts_kernel<<<(n_nodes + 255) / 256, 256>>>(n_nodes);
    hist_kernel<<<2048, 256>>>(dst, n_edges);

    // W split pre-pass + mma.sync GEMM -> g_support (fp16).
    wsplit_kernel<<<64, 256>>>(W);
    const int smem_bytes = 4 * 128 * PADK * 2;  // 139264
    cudaFuncSetAttribute(gemm_mma_kernel, cudaFuncAttributeMaxDynamicSharedMemorySize,
                         smem_bytes);
    gemm_mma_kernel<<<(n_nodes + 127) / 128, 256, smem_bytes>>>(X, n_nodes);

    scan1_kernel<<<nb, 256>>>(n_nodes);
    scan2_kernel<<<1, 128>>>(nb);
    scan3_kernel<<<(n_nodes + 255) / 256, 256>>>(n_nodes);
    fill_kernel<<<(n_edges + 255) / 256, 256>>>(vals, src, dst, n_edges);

    // Gather + ReLU.
    int blocks = (n_nodes * 32 + 255) / 256;
    gather_kernel<<<blocks, 256>>>(out, n_nodes);
}

// round 8
// speedup vs baseline: 1.2054x; 1.2054x over previous
#include <cuda_runtime.h>
#include <cuda_fp16.h>
#include <cuda_bf16.h>
#include <cstring>
#include <cstdint>

#define DIM 128
#define MAX_NODES 100000
#define MAX_EDGES 1600000
#define SCAN_BLK 1024
#define MAX_SCAN_BLOCKS 128
#define TILE_M 64   // GEMM rows per block

// Static device scratch (no allocs allowed).
__device__ __half g_support[MAX_NODES * DIM];           // 25.6 MB, L2-resident
__device__ int g_count[MAX_NODES];
__device__ int g_offset[MAX_NODES];
__device__ int g_cursor[MAX_NODES];
__device__ int g_blocksums[MAX_SCAN_BLOCKS];
__device__ unsigned long long g_bins[MAX_EDGES];        // (val<<32)|src, 12.8 MB
// Pre-split, pre-transposed weights: g_W*[n][k] (bf16).
__device__ __nv_bfloat16 g_Whi[DIM * DIM];
__device__ __nv_bfloat16 g_Wlo[DIM * DIM];

__device__ __forceinline__ uint32_t smem_u32(const void* p) {
    uint32_t a;
    asm("{ .reg .u64 t; cvta.to.shared.u64 t, %1; cvt.u32.u64 %0, t; }"
        : "=r"(a) : "l"(p));
    return a;
}
__device__ __forceinline__ unsigned int pack_half2f(float a, float b) {
    __half2 h = __floats2half2_rn(a, b);
    unsigned int u;
    memcpy(&u, &h, 4);
    return u;
}
__device__ __forceinline__ void ldsm_x4(uint32_t& r0, uint32_t& r1,
                                        uint32_t& r2, uint32_t& r3, uint32_t addr) {
    asm volatile("ldmatrix.sync.aligned.m8n8.x4.shared.b16 {%0,%1,%2,%3}, [%4];"
                 : "=r"(r0), "=r"(r1), "=r"(r2), "=r"(r3) : "r"(addr));
}
__device__ __forceinline__ void mma_bf16(float* c, const uint32_t* a,
                                         uint32_t b0, uint32_t b1) {
    asm volatile("mma.sync.aligned.m16n8k16.row.col.f32.bf16.bf16.f32 "
                 "{%0,%1,%2,%3}, {%4,%5,%6,%7}, {%8,%9}, {%0,%1,%2,%3};"
                 : "+f"(c[0]), "+f"(c[1]), "+f"(c[2]), "+f"(c[3])
                 : "r"(a[0]), "r"(a[1]), "r"(a[2]), "r"(a[3]), "r"(b0), "r"(b1));
}

// XOR-swizzled byte offset for a [rows][128 bf16] tile (256B rows, 16B chunks).
// chunk' = chunk ^ (row & 7): conflict-free ldmatrix over 8-row groups.
__device__ __forceinline__ uint32_t swz(int row, int chunk) {
    return (uint32_t)(row * 256 + ((chunk ^ (row & 7)) << 4));
}

// ---------------------------------------------------------------------------
// W split/transpose pre-pass: g_W{hi,lo}[n][k] = bf16 hi/lo split of W[k][n].
// ---------------------------------------------------------------------------
__global__ void wsplit_kernel(const float* __restrict__ W) {
    int i = blockIdx.x * blockDim.x + threadIdx.x;
    if (i < DIM * DIM) {
        int k = i >> 7, n = i & 127;
        float w = W[i];
        __nv_bfloat16 h = __float2bfloat16(w);
        float lo = w - __bfloat162float(h);
        g_Whi[n * DIM + k] = h;
        g_Wlo[n * DIM + k] = __float2bfloat16(lo);
    }
}

// ---------------------------------------------------------------------------
// Tensor-core GEMM via mma.sync, bf16 hi/lo split (3 MMAs -> ~fp32 accurate).
// Block: 256 thr (8 warps) computes 64 rows x 128 cols.
// Warp grid 2(M) x 4(N): warp tile 32 rows x 32 cols.
// smem: Ahi/Alo (16KB ea) + Whi/Wlo (32KB ea) = 96KB -> 2 blocks/SM.
// ---------------------------------------------------------------------------
__global__ void __launch_bounds__(256) gemm_mma_kernel(const float* __restrict__ X,
                                                       int n_rows) {
    extern __shared__ char dsm[];
    char* sAhi = dsm;                 // 64 x 256B = 16KB
    char* sAlo = dsm + 16 * 1024;
    char* sWhi = dsm + 32 * 1024;     // 128 x 256B = 32KB
    char* sWlo = dsm + 64 * 1024;

    int tid = threadIdx.x;
    int warp = tid >> 5;
    int lane = tid & 31;
    int row0 = blockIdx.x * TILE_M;

    // Copy pre-split W [n][k] into swizzled smem. FULL row = 16 chunks of 16B.
    for (int i = tid; i < 128 * 16; i += 256) {
        int n = i >> 4;
        int kc = i & 15;
        uint32_t off = swz(n, kc);
        *reinterpret_cast<uint4*>(sWhi + off) =
            *reinterpret_cast<const uint4*>(g_Whi + n * DIM + kc * 8);
        *reinterpret_cast<uint4*>(sWlo + off) =
            *reinterpret_cast<const uint4*>(g_Wlo + n * DIM + kc * 8);
    }

    // Load X tile, split to bf16 hi/lo, store swizzled (uint2 = half chunk).
    for (int i = tid; i < TILE_M * 32; i += 256) {
        int r = i >> 5;
        int k4 = i & 31;                       // group of 4 elements
        float4 v = make_float4(0.f, 0.f, 0.f, 0.f);
        if (row0 + r < n_rows)
            v = *reinterpret_cast<const float4*>(X + (size_t)(row0 + r) * DIM + k4 * 4);
        const float* vp = reinterpret_cast<const float*>(&v);
        __nv_bfloat16 h[4], l[4];
#pragma unroll
        for (int j = 0; j < 4; j++) {
            h[j] = __float2bfloat16(vp[j]);
            l[j] = __float2bfloat16(vp[j] - __bfloat162float(h[j]));
        }
        uint2 ph, pl;
        memcpy(&ph, h, 8);
        memcpy(&pl, l, 8);
        uint32_t off = swz(r, k4 >> 1) + (k4 & 1) * 8;
        *reinterpret_cast<uint2*>(sAhi + off) = ph;
        *reinterpret_cast<uint2*>(sAlo + off) = pl;
    }
    __syncthreads();

    int wm = warp & 1;            // 2-way M split
    int wn = warp >> 1;           // 4-way N split
    int mrow = wm * 32;
    int ncol = wn * 32;

    float acc[2][4][4];
#pragma unroll
    for (int mt = 0; mt < 2; mt++)
#pragma unroll
        for (int nt = 0; nt < 4; nt++)
#pragma unroll
            for (int q = 0; q < 4; q++) acc[mt][nt][q] = 0.f;

    uint32_t aHi = smem_u32(sAhi), aLo = smem_u32(sAlo);
    uint32_t wHi = smem_u32(sWhi), wLo = smem_u32(sWlo);

    // ldmatrix lane patterns (identical to the R6-validated kernel).
    int a_r = lane & 15;                       // row within m16 tile
    int a_c = lane >> 4;                       // 0/1 -> +8 k chunk
    int b_n = ((lane >> 4) << 3) + (lane & 7); // n within 16-col pair
    int b_c = (lane >> 3) & 1;                 // 0/1 -> +8 k chunk

#pragma unroll
    for (int ks = 0; ks < 8; ks++) {
        int c0 = ks * 2;   // 16B-chunk index of k0

        uint32_t ahi[2][4], alo[2][4];
#pragma unroll
        for (int mt = 0; mt < 2; mt++) {
            int rl = mrow + mt * 16 + a_r;
            uint32_t off = swz(rl, c0 + a_c);
            ldsm_x4(ahi[mt][0], ahi[mt][1], ahi[mt][2], ahi[mt][3], aHi + off);
            ldsm_x4(alo[mt][0], alo[mt][1], alo[mt][2], alo[mt][3], aLo + off);
        }

#pragma unroll
        for (int bp = 0; bp < 2; bp++) {       // 16-col pairs
            int nl = ncol + bp * 16 + b_n;
            uint32_t off = swz(nl, c0 + b_c);
            uint32_t h0, h1, h2, h3, l0, l1, l2, l3;
            ldsm_x4(h0, h1, h2, h3, wHi + off);
            ldsm_x4(l0, l1, l2, l3, wLo + off);
            int nt0 = bp * 2, nt1 = bp * 2 + 1;
#pragma unroll
            for (int mt = 0; mt < 2; mt++) {
                mma_bf16(acc[mt][nt0], ahi[mt], h0, h1);
                mma_bf16(acc[mt][nt0], ahi[mt], l0, l1);
                mma_bf16(acc[mt][nt0], alo[mt], h0, h1);
                mma_bf16(acc[mt][nt1], ahi[mt], h2, h3);
                mma_bf16(acc[mt][nt1], ahi[mt], l2, l3);
                mma_bf16(acc[mt][nt1], alo[mt], h2, h3);
            }
        }
    }

    // Epilogue: c-frag (row = lane>>2 [+8], col = (lane&3)*2) -> fp16 g_support.
#pragma unroll
    for (int mt = 0; mt < 2; mt++) {
        int r0g = row0 + mrow + mt * 16 + (lane >> 2);
        int r1g = r0g + 8;
#pragma unroll
        for (int nt = 0; nt < 4; nt++) {
            int col = ncol + nt * 8 + (lane & 3) * 2;
            if (r0g < n_rows)
                *reinterpret_cast<unsigned int*>(g_support + (size_t)r0g * DIM + col) =
                    pack_half2f(acc[mt][nt][0], acc[mt][nt][1]);
            if (r1g < n_rows)
                *reinterpret_cast<unsigned int*>(g_support + (size_t)r1g * DIM + col) =
                    pack_half2f(acc[mt][nt][2], acc[mt][nt][3]);
        }
    }
}

// ---------------------------------------------------------------------------
// CSR binning: zero counts -> histogram -> 3-phase exclusive scan -> fill.
// ---------------------------------------------------------------------------
__global__ void zero_counts_kernel(int n_nodes) {
    int i = blockIdx.x * blockDim.x + threadIdx.x;
    if (i < n_nodes) g_count[i] = 0;
}

__global__ void hist_kernel(const int* __restrict__ dst, int n_edges) {
    int i = blockIdx.x * blockDim.x + threadIdx.x;
    int stride = gridDim.x * blockDim.x;
    for (; i < n_edges; i += stride)
        atomicAdd(&g_count[dst[i]], 1);
}

__global__ void __launch_bounds__(256) scan1_kernel(int n_nodes) {
    __shared__ int s[256];
    int base = blockIdx.x * SCAN_BLK;
    int t = threadIdx.x;
    int v[4];
    int sum = 0;
#pragma unroll
    for (int j = 0; j < 4; j++) {
        int idx = base + t * 4 + j;
        v[j] = (idx < n_nodes) ? g_count[idx] : 0;
        sum += v[j];
    }
    s[t] = sum;
    __syncthreads();
    for (int off = 1; off < 256; off <<= 1) {
        int x = (t >= off) ? s[t - off] : 0;
        __syncthreads();
        s[t] += x;
        __syncthreads();
    }
    int excl = s[t] - sum;
    if (t == 255) g_blocksums[blockIdx.x] = s[255];
    int run = excl;
#pragma unroll
    for (int j = 0; j < 4; j++) {
        int idx = base + t * 4 + j;
        if (idx < n_nodes) g_offset[idx] = run;
        run += v[j];
    }
}

__global__ void __launch_bounds__(128) scan2_kernel(int nb) {
    __shared__ int s[128];
    int t = threadIdx.x;
    int v = (t < nb) ? g_blocksums[t] : 0;
    s[t] = v;
    __syncthreads();
    for (int off = 1; off < 128; off <<= 1) {
        int x = (t >= off) ? s[t - off] : 0;
        __syncthreads();
        s[t] += x;
        __syncthreads();
    }
    if (t < nb) g_blocksums[t] = s[t] - v;
}

__global__ void scan3_kernel(int n_nodes) {
    int i = blockIdx.x * blockDim.x + threadIdx.x;
    if (i < n_nodes) {
        int o = g_offset[i] + g_blocksums[i / SCAN_BLK];
        g_offset[i] = o;
        g_cursor[i] = o;
    }
}

__global__ void fill_kernel(const float* __restrict__ vals,
                            const int* __restrict__ src,
                            const int* __restrict__ dst,
                            int n_edges) {
    int i = blockIdx.x * blockDim.x + threadIdx.x;
    if (i < n_edges) {
        int d = dst[i];
        int pos = atomicAdd(&g_cursor[d], 1);
        g_bins[pos] = ((unsigned long long)__float_as_uint(vals[i]) << 32) |
                      (unsigned int)src[i];
    }
}

// ---------------------------------------------------------------------------
// Gather: one warp per dst node, 4-edge pipeline, fused ReLU, single write.
// ---------------------------------------------------------------------------
__global__ void __launch_bounds__(256) gather_kernel(float* __restrict__ out,
                                                     int n_nodes) {
    int warp = (blockIdx.x * blockDim.x + threadIdx.x) >> 5;
    int lane = threadIdx.x & 31;
    if (warp >= n_nodes) return;

    int o0 = g_offset[warp];
    int deg = g_count[warp];

    float4 acc = make_float4(0.f, 0.f, 0.f, 0.f);

    for (int e = 0; e < deg; e += 4) {
        unsigned long long p[4];
#pragma unroll
        for (int j = 0; j < 4; j++)
            p[j] = (e + j < deg) ? __ldg(g_bins + o0 + e + j) : 0ull;

        uint2 hv[4];
#pragma unroll
        for (int j = 0; j < 4; j++) {
            int s = (int)(p[j] & 0xffffffffull);
            hv[j] = __ldg(reinterpret_cast<const uint2*>(
                g_support + (size_t)s * DIM + lane * 4));
        }
#pragma unroll
        for (int j = 0; j < 4; j++) {
            float v = __uint_as_float((unsigned int)(p[j] >> 32));
            __half2 a, b;
            memcpy(&a, &hv[j].x, 4);
            memcpy(&b, &hv[j].y, 4);
            float2 fa = __half22float2(a);
            float2 fb = __half22float2(b);
            acc.x = fmaf(v, fa.x, acc.x);
            acc.y = fmaf(v, fa.y, acc.y);
            acc.z = fmaf(v, fb.x, acc.z);
            acc.w = fmaf(v, fb.y, acc.w);
        }
    }

    acc.x = fmaxf(acc.x, 0.f);
    acc.y = fmaxf(acc.y, 0.f);
    acc.z = fmaxf(acc.z, 0.f);
    acc.w = fmaxf(acc.w, 0.f);
    *reinterpret_cast<float4*>(out + (size_t)warp * DIM + lane * 4) = acc;
}

extern "C" void kernel_launch(void* const* d_in, const int* in_sizes, int n_in,
                              void* d_out, int out_size) {
    const float* X    = (const float*)d_in[0];   // [n_nodes, 128]
    const float* W    = (const float*)d_in[1];   // [128, 128]
    const float* vals = (const float*)d_in[2];   // [E]
    const int*   src  = (const int*)d_in[3];     // [E]
    const int*   dst  = (const int*)d_in[4];     // [E]
    float* out = (float*)d_out;

    int n_nodes = in_sizes[0] / DIM;
    int n_edges = in_sizes[2];
    int nb = (n_nodes + SCAN_BLK - 1) / SCAN_BLK;

    // Binning pipeline front half.
    zero_counts_kernel<<<(n_nodes + 255) / 256, 256>>>(n_nodes);
    hist_kernel<<<2048, 256>>>(dst, n_edges);

    // W split pre-pass + mma.sync GEMM -> g_support (fp16).
    wsplit_kernel<<<64, 256>>>(W);
    const int smem_bytes = 96 * 1024;
    cudaFuncSetAttribute(gemm_mma_kernel, cudaFuncAttributeMaxDynamicSharedMemorySize,
                         smem_bytes);
    gemm_mma_kernel<<<(n_nodes + TILE_M - 1) / TILE_M, 256, smem_bytes>>>(X, n_nodes);

    scan1_kernel<<<nb, 256>>>(n_nodes);
    scan2_kernel<<<1, 128>>>(nb);
    scan3_kernel<<<(n_nodes + 255) / 256, 256>>>(n_nodes);
    fill_kernel<<<(n_edges + 255) / 256, 256>>>(vals, src, dst, n_edges);

    // Gather + ReLU.
    int blocks = (n_nodes * 32 + 255) / 256;
    gather_kernel<<<blocks, 256>>>(out, n_nodes);
}

// round 9
// speedup vs baseline: 1.4093x; 1.1691x over previous
#include <cuda_runtime.h>
#include <cuda_fp16.h>
#include <cuda_bf16.h>
#include <cstring>
#include <cstdint>

#define DIM 128
#define MAX_NODES 100000
#define MAX_EDGES 1600000
#define SCAN_BLK 1024
#define MAX_SCAN_BLOCKS 128
#define TILE_M 32   // GEMM rows per block

// Static device scratch (no allocs allowed).
__device__ __half g_support[MAX_NODES * DIM];           // 25.6 MB, L2-resident
__device__ int g_count[MAX_NODES];
__device__ int g_offset[MAX_NODES];
__device__ int g_cursor[MAX_NODES];
__device__ int g_blocksums[MAX_SCAN_BLOCKS];
__device__ unsigned long long g_bins[MAX_EDGES];        // (val<<32)|src, 12.8 MB
// W pre-packed in mma B-fragment order: [(wn*8+ks)*32 + lane] -> {h0,h1,h2,h3}.
__device__ uint4 g_WfragHi[8 * 8 * 32];                 // 32KB
__device__ uint4 g_WfragLo[8 * 8 * 32];                 // 32KB

__device__ __forceinline__ uint32_t smem_u32(const void* p) {
    uint32_t a;
    asm("{ .reg .u64 t; cvta.to.shared.u64 t, %1; cvt.u32.u64 %0, t; }"
        : "=r"(a) : "l"(p));
    return a;
}
__device__ __forceinline__ unsigned int pack_half2f(float a, float b) {
    __half2 h = __floats2half2_rn(a, b);
    unsigned int u;
    memcpy(&u, &h, 4);
    return u;
}
__device__ __forceinline__ unsigned int pack_bf2(__nv_bfloat16 a, __nv_bfloat16 b) {
    __nv_bfloat162 h;
    h.x = a; h.y = b;
    unsigned int u;
    memcpy(&u, &h, 4);
    return u;
}
__device__ __forceinline__ void ldsm_x4(uint32_t& r0, uint32_t& r1,
                                        uint32_t& r2, uint32_t& r3, uint32_t addr) {
    asm volatile("ldmatrix.sync.aligned.m8n8.x4.shared.b16 {%0,%1,%2,%3}, [%4];"
                 : "=r"(r0), "=r"(r1), "=r"(r2), "=r"(r3) : "r"(addr));
}
__device__ __forceinline__ void mma_bf16(float* c, const uint32_t* a,
                                         uint32_t b0, uint32_t b1) {
    asm volatile("mma.sync.aligned.m16n8k16.row.col.f32.bf16.bf16.f32 "
                 "{%0,%1,%2,%3}, {%4,%5,%6,%7}, {%8,%9}, {%0,%1,%2,%3};"
                 : "+f"(c[0]), "+f"(c[1]), "+f"(c[2]), "+f"(c[3])
                 : "r"(a[0]), "r"(a[1]), "r"(a[2]), "r"(a[3]), "r"(b0), "r"(b1));
}

// XOR-swizzled byte offset for a [rows][128 bf16] tile (256B rows, 16B chunks).
__device__ __forceinline__ uint32_t swz(int row, int chunk) {
    return (uint32_t)(row * 256 + ((chunk ^ (row & 7)) << 4));
}

// ---------------------------------------------------------------------------
// W fragment pre-pass. For warp-col wn (0..7), k-step ks (0..7), lane l:
// frag rows n0 = wn*16, matrix row = l/4, cols k0+2*(l%4) (+1).
//   h0: (n0 + l/4,     k0 + 2m)   h1: same n, k+8
//   h2: (n0 + 8 + l/4, k0 + 2m)   h3: same n, k+8
// Derived 1:1 from the validated R8 ldmatrix address pattern.
// ---------------------------------------------------------------------------
__global__ void wfrag_kernel(const float* __restrict__ W) {
    int idx = blockIdx.x * blockDim.x + threadIdx.x;   // 0..2047
    if (idx >= 8 * 8 * 32) return;
    int lane = idx & 31;
    int ks = (idx >> 5) & 7;
    int wn = idx >> 8;
    int m = lane & 3;
    int r = lane >> 2;          // 0..7
    int k0 = ks * 16 + 2 * m;
    int n0 = wn * 16 + r;

    uint4 hi, lo;
    unsigned int* hp = reinterpret_cast<unsigned int*>(&hi);
    unsigned int* lp = reinterpret_cast<unsigned int*>(&lo);
#pragma unroll
    for (int f = 0; f < 4; f++) {
        int n = n0 + ((f >> 1) << 3);       // +8 rows for h2/h3
        int k = k0 + ((f & 1) << 3);        // +8 cols for h1/h3
        float w0 = W[k * DIM + n];
        float w1 = W[(k + 1) * DIM + n];
        __nv_bfloat16 h0 = __float2bfloat16(w0);
        __nv_bfloat16 h1 = __float2bfloat16(w1);
        __nv_bfloat16 l0 = __float2bfloat16(w0 - __bfloat162float(h0));
        __nv_bfloat16 l1 = __float2bfloat16(w1 - __bfloat162float(h1));
        hp[f] = pack_bf2(h0, h1);
        lp[f] = pack_bf2(l0, l1);
    }
    g_WfragHi[idx] = hi;
    g_WfragLo[idx] = lo;
}

// ---------------------------------------------------------------------------
// Tensor-core GEMM. Block: 256 thr (8 warps), 32 rows x 128 cols.
// Each warp: full 32 rows (mt=2) x 16 cols (nt=2), W frags via direct LDG
// from L2-resident g_Wfrag (no W smem, no W ldmatrix).
// smem: A hi/lo only, 16KB static -> occupancy register-limited (~3-4 blk/SM).
// ---------------------------------------------------------------------------
__global__ void __launch_bounds__(256) gemm_mma_kernel(const float* __restrict__ X,
                                                       int n_rows) {
    __shared__ char sAhi[TILE_M * 256];   // 8KB, swizzled
    __shared__ char sAlo[TILE_M * 256];   // 8KB

    int tid = threadIdx.x;
    int warp = tid >> 5;
    int lane = tid & 31;
    int row0 = blockIdx.x * TILE_M;

    // Load X tile, split to bf16 hi/lo, store swizzled (uint2 = half chunk).
    for (int i = tid; i < TILE_M * 32; i += 256) {
        int r = i >> 5;
        int k4 = i & 31;
        float4 v = make_float4(0.f, 0.f, 0.f, 0.f);
        if (row0 + r < n_rows)
            v = *reinterpret_cast<const float4*>(X + (size_t)(row0 + r) * DIM + k4 * 4);
        const float* vp = reinterpret_cast<const float*>(&v);
        __nv_bfloat16 h[4], l[4];
#pragma unroll
        for (int j = 0; j < 4; j++) {
            h[j] = __float2bfloat16(vp[j]);
            l[j] = __float2bfloat16(vp[j] - __bfloat162float(h[j]));
        }
        uint2 ph, pl;
        memcpy(&ph, h, 8);
        memcpy(&pl, l, 8);
        uint32_t off = swz(r, k4 >> 1) + (k4 & 1) * 8;
        *reinterpret_cast<uint2*>(sAhi + off) = ph;
        *reinterpret_cast<uint2*>(sAlo + off) = pl;
    }
    __syncthreads();

    float acc[2][2][4];
#pragma unroll
    for (int mt = 0; mt < 2; mt++)
#pragma unroll
        for (int nt = 0; nt < 2; nt++)
#pragma unroll
            for (int q = 0; q < 4; q++) acc[mt][nt][q] = 0.f;

    uint32_t aHi = smem_u32(sAhi), aLo = smem_u32(sAlo);

    int a_r = lane & 15;                       // row within m16 tile
    int a_c = lane >> 4;                       // 0/1 -> +8 k chunk

#pragma unroll
    for (int ks = 0; ks < 8; ks++) {
        int c0 = ks * 2;

        uint4 bh = __ldg(&g_WfragHi[(warp * 8 + ks) * 32 + lane]);
        uint4 bl = __ldg(&g_WfragLo[(warp * 8 + ks) * 32 + lane]);

        uint32_t ahi[2][4], alo[2][4];
#pragma unroll
        for (int mt = 0; mt < 2; mt++) {
            int rl = mt * 16 + a_r;
            uint32_t off = swz(rl, c0 + a_c);
            ldsm_x4(ahi[mt][0], ahi[mt][1], ahi[mt][2], ahi[mt][3], aHi + off);
            ldsm_x4(alo[mt][0], alo[mt][1], alo[mt][2], alo[mt][3], aLo + off);
        }

#pragma unroll
        for (int mt = 0; mt < 2; mt++) {
            mma_bf16(acc[mt][0], ahi[mt], bh.x, bh.y);
            mma_bf16(acc[mt][0], ahi[mt], bl.x, bl.y);
            mma_bf16(acc[mt][0], alo[mt], bh.x, bh.y);
            mma_bf16(acc[mt][1], ahi[mt], bh.z, bh.w);
            mma_bf16(acc[mt][1], ahi[mt], bl.z, bl.w);
            mma_bf16(acc[mt][1], alo[mt], bh.z, bh.w);
        }
    }

    // Epilogue: c-frag (row = lane>>2 [+8], col = (lane&3)*2) -> fp16 g_support.
    int ncol = warp * 16;
#pragma unroll
    for (int mt = 0; mt < 2; mt++) {
        int r0g = row0 + mt * 16 + (lane >> 2);
        int r1g = r0g + 8;
#pragma unroll
        for (int nt = 0; nt < 2; nt++) {
            int col = ncol + nt * 8 + (lane & 3) * 2;
            if (r0g < n_rows)
                *reinterpret_cast<unsigned int*>(g_support + (size_t)r0g * DIM + col) =
                    pack_half2f(acc[mt][nt][0], acc[mt][nt][1]);
            if (r1g < n_rows)
                *reinterpret_cast<unsigned int*>(g_support + (size_t)r1g * DIM + col) =
                    pack_half2f(acc[mt][nt][2], acc[mt][nt][3]);
        }
    }
}

// ---------------------------------------------------------------------------
// CSR binning: zero counts -> histogram -> 3-phase exclusive scan -> fill.
// ---------------------------------------------------------------------------
__global__ void zero_counts_kernel(int n_nodes) {
    int i = blockIdx.x * blockDim.x + threadIdx.x;
    if (i < n_nodes) g_count[i] = 0;
}

__global__ void hist_kernel(const int* __restrict__ dst, int n_edges) {
    int i = blockIdx.x * blockDim.x + threadIdx.x;
    int stride = gridDim.x * blockDim.x;
    for (; i < n_edges; i += stride)
        atomicAdd(&g_count[dst[i]], 1);
}

__global__ void __launch_bounds__(256) scan1_kernel(int n_nodes) {
    __shared__ int s[256];
    int base = blockIdx.x * SCAN_BLK;
    int t = threadIdx.x;
    int v[4];
    int sum = 0;
#pragma unroll
    for (int j = 0; j < 4; j++) {
        int idx = base + t * 4 + j;
        v[j] = (idx < n_nodes) ? g_count[idx] : 0;
        sum += v[j];
    }
    s[t] = sum;
    __syncthreads();
    for (int off = 1; off < 256; off <<= 1) {
        int x = (t >= off) ? s[t - off] : 0;
        __syncthreads();
        s[t] += x;
        __syncthreads();
    }
    int excl = s[t] - sum;
    if (t == 255) g_blocksums[blockIdx.x] = s[255];
    int run = excl;
#pragma unroll
    for (int j = 0; j < 4; j++) {
        int idx = base + t * 4 + j;
        if (idx < n_nodes) g_offset[idx] = run;
        run += v[j];
    }
}

__global__ void __launch_bounds__(128) scan2_kernel(int nb) {
    __shared__ int s[128];
    int t = threadIdx.x;
    int v = (t < nb) ? g_blocksums[t] : 0;
    s[t] = v;
    __syncthreads();
    for (int off = 1; off < 128; off <<= 1) {
        int x = (t >= off) ? s[t - off] : 0;
        __syncthreads();
        s[t] += x;
        __syncthreads();
    }
    if (t < nb) g_blocksums[t] = s[t] - v;
}

__global__ void scan3_kernel(int n_nodes) {
    int i = blockIdx.x * blockDim.x + threadIdx.x;
    if (i < n_nodes) {
        int o = g_offset[i] + g_blocksums[i / SCAN_BLK];
        g_offset[i] = o;
        g_cursor[i] = o;
    }
}

__global__ void fill_kernel(const float* __restrict__ vals,
                            const int* __restrict__ src,
                            const int* __restrict__ dst,
                            int n_edges) {
    int i = blockIdx.x * blockDim.x + threadIdx.x;
    if (i < n_edges) {
        int d = dst[i];
        int pos = atomicAdd(&g_cursor[d], 1);
        g_bins[pos] = ((unsigned long long)__float_as_uint(vals[i]) << 32) |
                      (unsigned int)src[i];
    }
}

// ---------------------------------------------------------------------------
// Gather: one warp per dst node, 4-edge pipeline, fused ReLU, single write.
// ---------------------------------------------------------------------------
__global__ void __launch_bounds__(256) gather_kernel(float* __restrict__ out,
                                                     int n_nodes) {
    int warp = (blockIdx.x * blockDim.x + threadIdx.x) >> 5;
    int lane = threadIdx.x & 31;
    if (warp >= n_nodes) return;

    int o0 = g_offset[warp];
    int deg = g_count[warp];

    float4 acc = make_float4(0.f, 0.f, 0.f, 0.f);

    for (int e = 0; e < deg; e += 4) {
        unsigned long long p[4];
#pragma unroll
        for (int j = 0; j < 4; j++)
            p[j] = (e + j < deg) ? __ldg(g_bins + o0 + e + j) : 0ull;

        uint2 hv[4];
#pragma unroll
        for (int j = 0; j < 4; j++) {
            int s = (int)(p[j] & 0xffffffffull);
            hv[j] = __ldg(reinterpret_cast<const uint2*>(
                g_support + (size_t)s * DIM + lane * 4));
        }
#pragma unroll
        for (int j = 0; j < 4; j++) {
            float v = __uint_as_float((unsigned int)(p[j] >> 32));
            __half2 a, b;
            memcpy(&a, &hv[j].x, 4);
            memcpy(&b, &hv[j].y, 4);
            float2 fa = __half22float2(a);
            float2 fb = __half22float2(b);
            acc.x = fmaf(v, fa.x, acc.x);
            acc.y = fmaf(v, fa.y, acc.y);
            acc.z = fmaf(v, fb.x, acc.z);
            acc.w = fmaf(v, fb.y, acc.w);
        }
    }

    acc.x = fmaxf(acc.x, 0.f);
    acc.y = fmaxf(acc.y, 0.f);
    acc.z = fmaxf(acc.z, 0.f);
    acc.w = fmaxf(acc.w, 0.f);
    *reinterpret_cast<float4*>(out + (size_t)warp * DIM + lane * 4) = acc;
}

extern "C" void kernel_launch(void* const* d_in, const int* in_sizes, int n_in,
                              void* d_out, int out_size) {
    const float* X    = (const float*)d_in[0];   // [n_nodes, 128]
    const float* W    = (const float*)d_in[1];   // [128, 128]
    const float* vals = (const float*)d_in[2];   // [E]
    const int*   src  = (const int*)d_in[3];     // [E]
    const int*   dst  = (const int*)d_in[4];     // [E]
    float* out = (float*)d_out;

    int n_nodes = in_sizes[0] / DIM;
    int n_edges = in_sizes[2];
    int nb = (n_nodes + SCAN_BLK - 1) / SCAN_BLK;

    // Binning pipeline front half.
    zero_counts_kernel<<<(n_nodes + 255) / 256, 256>>>(n_nodes);
    hist_kernel<<<2048, 256>>>(dst, n_edges);

    // W fragment pre-pass + mma.sync GEMM -> g_support (fp16).
    wfrag_kernel<<<8, 256>>>(W);
    gemm_mma_kernel<<<(n_nodes + TILE_M - 1) / TILE_M, 256>>>(X, n_nodes);

    scan1_kernel<<<nb, 256>>>(n_nodes);
    scan2_kernel<<<1, 128>>>(nb);
    scan3_kernel<<<(n_nodes + 255) / 256, 256>>>(n_nodes);
    fill_kernel<<<(n_edges + 255) / 256, 256>>>(vals, src, dst, n_edges);

    // Gather + ReLU.
    int blocks = (n_nodes * 32 + 255) / 256;
    gather_kernel<<<blocks, 256>>>(out, n_nodes);
}

// round 10
// speedup vs baseline: 1.4651x; 1.0395x over previous
#include <cuda_runtime.h>
#include <cuda_fp16.h>
#include <cuda_bf16.h>
#include <cstring>
#include <cstdint>

#define DIM 128
#define MAX_NODES 100000
#define MAX_EDGES 1600000
#define SCAN_BLK 1024
#define MAX_SCAN_BLOCKS 128
#define TILE_M 32   // GEMM rows per block

// Static device scratch (no allocs allowed).
__device__ __half g_support[MAX_NODES * DIM];           // 25.6 MB, L2-resident
__device__ int g_count[MAX_NODES];
__device__ int g_offset[MAX_NODES];
__device__ int g_cursor[MAX_NODES];
__device__ int g_blocksums[MAX_SCAN_BLOCKS];
__device__ unsigned long long g_bins[MAX_EDGES];        // (val<<32)|src, 12.8 MB
// W pre-packed in mma B-fragment order: [(wn*8+ks)*32 + lane] -> {h0,h1,h2,h3}.
__device__ uint4 g_WfragHi[8 * 8 * 32];                 // 32KB
__device__ uint4 g_WfragLo[8 * 8 * 32];                 // 32KB

__device__ __forceinline__ uint32_t smem_u32(const void* p) {
    uint32_t a;
    asm("{ .reg .u64 t; cvta.to.shared.u64 t, %1; cvt.u32.u64 %0, t; }"
        : "=r"(a) : "l"(p));
    return a;
}
__device__ __forceinline__ unsigned int pack_half2f(float a, float b) {
    __half2 h = __floats2half2_rn(a, b);
    unsigned int u;
    memcpy(&u, &h, 4);
    return u;
}
__device__ __forceinline__ unsigned int pack_bf2(__nv_bfloat16 a, __nv_bfloat16 b) {
    __nv_bfloat162 h;
    h.x = a; h.y = b;
    unsigned int u;
    memcpy(&u, &h, 4);
    return u;
}
__device__ __forceinline__ void ldsm_x4(uint32_t& r0, uint32_t& r1,
                                        uint32_t& r2, uint32_t& r3, uint32_t addr) {
    asm volatile("ldmatrix.sync.aligned.m8n8.x4.shared.b16 {%0,%1,%2,%3}, [%4];"
                 : "=r"(r0), "=r"(r1), "=r"(r2), "=r"(r3) : "r"(addr));
}
__device__ __forceinline__ void mma_bf16(float* c, const uint32_t* a,
                                         uint32_t b0, uint32_t b1) {
    asm volatile("mma.sync.aligned.m16n8k16.row.col.f32.bf16.bf16.f32 "
                 "{%0,%1,%2,%3}, {%4,%5,%6,%7}, {%8,%9}, {%0,%1,%2,%3};"
                 : "+f"(c[0]), "+f"(c[1]), "+f"(c[2]), "+f"(c[3])
                 : "r"(a[0]), "r"(a[1]), "r"(a[2]), "r"(a[3]), "r"(b0), "r"(b1));
}

// XOR-swizzled byte offset for a [rows][128 bf16] tile (256B rows, 16B chunks).
__device__ __forceinline__ uint32_t swz(int row, int chunk) {
    return (uint32_t)(row * 256 + ((chunk ^ (row & 7)) << 4));
}

// ---------------------------------------------------------------------------
// W fragment pre-pass (validated R9): B-fragment order, bf16 hi/lo split.
// ---------------------------------------------------------------------------
__global__ void wfrag_kernel(const float* __restrict__ W) {
    int idx = blockIdx.x * blockDim.x + threadIdx.x;   // 0..2047
    if (idx >= 8 * 8 * 32) return;
    int lane = idx & 31;
    int ks = (idx >> 5) & 7;
    int wn = idx >> 8;
    int m = lane & 3;
    int r = lane >> 2;
    int k0 = ks * 16 + 2 * m;
    int n0 = wn * 16 + r;

    uint4 hi, lo;
    unsigned int* hp = reinterpret_cast<unsigned int*>(&hi);
    unsigned int* lp = reinterpret_cast<unsigned int*>(&lo);
#pragma unroll
    for (int f = 0; f < 4; f++) {
        int n = n0 + ((f >> 1) << 3);
        int k = k0 + ((f & 1) << 3);
        float w0 = W[k * DIM + n];
        float w1 = W[(k + 1) * DIM + n];
        __nv_bfloat16 h0 = __float2bfloat16(w0);
        __nv_bfloat16 h1 = __float2bfloat16(w1);
        __nv_bfloat16 l0 = __float2bfloat16(w0 - __bfloat162float(h0));
        __nv_bfloat16 l1 = __float2bfloat16(w1 - __bfloat162float(h1));
        hp[f] = pack_bf2(h0, h1);
        lp[f] = pack_bf2(l0, l1);
    }
    g_WfragHi[idx] = hi;
    g_WfragLo[idx] = lo;
}

// ---------------------------------------------------------------------------
// Tensor-core GEMM (validated R9): 32 rows/block, W frags via L2 LDG.
// ---------------------------------------------------------------------------
__global__ void __launch_bounds__(256) gemm_mma_kernel(const float* __restrict__ X,
                                                       int n_rows) {
    __shared__ char sAhi[TILE_M * 256];
    __shared__ char sAlo[TILE_M * 256];

    int tid = threadIdx.x;
    int warp = tid >> 5;
    int lane = tid & 31;
    int row0 = blockIdx.x * TILE_M;

    for (int i = tid; i < TILE_M * 32; i += 256) {
        int r = i >> 5;
        int k4 = i & 31;
        float4 v = make_float4(0.f, 0.f, 0.f, 0.f);
        if (row0 + r < n_rows)
            v = *reinterpret_cast<const float4*>(X + (size_t)(row0 + r) * DIM + k4 * 4);
        const float* vp = reinterpret_cast<const float*>(&v);
        __nv_bfloat16 h[4], l[4];
#pragma unroll
        for (int j = 0; j < 4; j++) {
            h[j] = __float2bfloat16(vp[j]);
            l[j] = __float2bfloat16(vp[j] - __bfloat162float(h[j]));
        }
        uint2 ph, pl;
        memcpy(&ph, h, 8);
        memcpy(&pl, l, 8);
        uint32_t off = swz(r, k4 >> 1) + (k4 & 1) * 8;
        *reinterpret_cast<uint2*>(sAhi + off) = ph;
        *reinterpret_cast<uint2*>(sAlo + off) = pl;
    }
    __syncthreads();

    float acc[2][2][4];
#pragma unroll
    for (int mt = 0; mt < 2; mt++)
#pragma unroll
        for (int nt = 0; nt < 2; nt++)
#pragma unroll
            for (int q = 0; q < 4; q++) acc[mt][nt][q] = 0.f;

    uint32_t aHi = smem_u32(sAhi), aLo = smem_u32(sAlo);

    int a_r = lane & 15;
    int a_c = lane >> 4;

#pragma unroll
    for (int ks = 0; ks < 8; ks++) {
        int c0 = ks * 2;

        uint4 bh = __ldg(&g_WfragHi[(warp * 8 + ks) * 32 + lane]);
        uint4 bl = __ldg(&g_WfragLo[(warp * 8 + ks) * 32 + lane]);

        uint32_t ahi[2][4], alo[2][4];
#pragma unroll
        for (int mt = 0; mt < 2; mt++) {
            int rl = mt * 16 + a_r;
            uint32_t off = swz(rl, c0 + a_c);
            ldsm_x4(ahi[mt][0], ahi[mt][1], ahi[mt][2], ahi[mt][3], aHi + off);
            ldsm_x4(alo[mt][0], alo[mt][1], alo[mt][2], alo[mt][3], aLo + off);
        }

#pragma unroll
        for (int mt = 0; mt < 2; mt++) {
            mma_bf16(acc[mt][0], ahi[mt], bh.x, bh.y);
            mma_bf16(acc[mt][0], ahi[mt], bl.x, bl.y);
            mma_bf16(acc[mt][0], alo[mt], bh.x, bh.y);
            mma_bf16(acc[mt][1], ahi[mt], bh.z, bh.w);
            mma_bf16(acc[mt][1], ahi[mt], bl.z, bl.w);
            mma_bf16(acc[mt][1], alo[mt], bh.z, bh.w);
        }
    }

    int ncol = warp * 16;
#pragma unroll
    for (int mt = 0; mt < 2; mt++) {
        int r0g = row0 + mt * 16 + (lane >> 2);
        int r1g = r0g + 8;
#pragma unroll
        for (int nt = 0; nt < 2; nt++) {
            int col = ncol + nt * 8 + (lane & 3) * 2;
            if (r0g < n_rows)
                *reinterpret_cast<unsigned int*>(g_support + (size_t)r0g * DIM + col) =
                    pack_half2f(acc[mt][nt][0], acc[mt][nt][1]);
            if (r1g < n_rows)
                *reinterpret_cast<unsigned int*>(g_support + (size_t)r1g * DIM + col) =
                    pack_half2f(acc[mt][nt][2], acc[mt][nt][3]);
        }
    }
}

// ---------------------------------------------------------------------------
// CSR binning: zero counts -> histogram -> 3-phase exclusive scan -> fill.
// ---------------------------------------------------------------------------
__global__ void zero_counts_kernel(int n_nodes) {
    int i = blockIdx.x * blockDim.x + threadIdx.x;
    if (i < n_nodes) g_count[i] = 0;
}

__global__ void hist_kernel(const int* __restrict__ dst, int n_edges) {
    int i = blockIdx.x * blockDim.x + threadIdx.x;
    int stride = gridDim.x * blockDim.x;
    for (; i < n_edges; i += stride)
        atomicAdd(&g_count[dst[i]], 1);
}

__global__ void __launch_bounds__(256) scan1_kernel(int n_nodes) {
    __shared__ int s[256];
    int base = blockIdx.x * SCAN_BLK;
    int t = threadIdx.x;
    int v[4];
    int sum = 0;
#pragma unroll
    for (int j = 0; j < 4; j++) {
        int idx = base + t * 4 + j;
        v[j] = (idx < n_nodes) ? g_count[idx] : 0;
        sum += v[j];
    }
    s[t] = sum;
    __syncthreads();
    for (int off = 1; off < 256; off <<= 1) {
        int x = (t >= off) ? s[t - off] : 0;
        __syncthreads();
        s[t] += x;
        __syncthreads();
    }
    int excl = s[t] - sum;
    if (t == 255) g_blocksums[blockIdx.x] = s[255];
    int run = excl;
#pragma unroll
    for (int j = 0; j < 4; j++) {
        int idx = base + t * 4 + j;
        if (idx < n_nodes) g_offset[idx] = run;
        run += v[j];
    }
}

__global__ void __launch_bounds__(128) scan2_kernel(int nb) {
    __shared__ int s[128];
    int t = threadIdx.x;
    int v = (t < nb) ? g_blocksums[t] : 0;
    s[t] = v;
    __syncthreads();
    for (int off = 1; off < 128; off <<= 1) {
        int x = (t >= off) ? s[t - off] : 0;
        __syncthreads();
        s[t] += x;
        __syncthreads();
    }
    if (t < nb) g_blocksums[t] = s[t] - v;
}

__global__ void scan3_kernel(int n_nodes) {
    int i = blockIdx.x * blockDim.x + threadIdx.x;
    if (i < n_nodes) {
        int o = g_offset[i] + g_blocksums[i / SCAN_BLK];
        g_offset[i] = o;
        g_cursor[i] = o;
    }
}

__global__ void fill_kernel(const float* __restrict__ vals,
                            const int* __restrict__ src,
                            const int* __restrict__ dst,
                            int n_edges) {
    int i = blockIdx.x * blockDim.x + threadIdx.x;
    if (i < n_edges) {
        int d = dst[i];
        int pos = atomicAdd(&g_cursor[d], 1);
        g_bins[pos] = ((unsigned long long)__float_as_uint(vals[i]) << 32) |
                      (unsigned int)src[i];
    }
}

// ---------------------------------------------------------------------------
// Gather: one warp per dst node, 4-edge pipeline, fused ReLU, single write.
// ---------------------------------------------------------------------------
__global__ void __launch_bounds__(256) gather_kernel(float* __restrict__ out,
                                                     int n_nodes) {
    int warp = (blockIdx.x * blockDim.x + threadIdx.x) >> 5;
    int lane = threadIdx.x & 31;
    if (warp >= n_nodes) return;

    int o0 = g_offset[warp];
    int deg = g_count[warp];

    float4 acc = make_float4(0.f, 0.f, 0.f, 0.f);

    for (int e = 0; e < deg; e += 4) {
        unsigned long long p[4];
#pragma unroll
        for (int j = 0; j < 4; j++)
            p[j] = (e + j < deg) ? __ldg(g_bins + o0 + e + j) : 0ull;

        uint2 hv[4];
#pragma unroll
        for (int j = 0; j < 4; j++) {
            int s = (int)(p[j] & 0xffffffffull);
            hv[j] = __ldg(reinterpret_cast<const uint2*>(
                g_support + (size_t)s * DIM + lane * 4));
        }
#pragma unroll
        for (int j = 0; j < 4; j++) {
            float v = __uint_as_float((unsigned int)(p[j] >> 32));
            __half2 a, b;
            memcpy(&a, &hv[j].x, 4);
            memcpy(&b, &hv[j].y, 4);
            float2 fa = __half22float2(a);
            float2 fb = __half22float2(b);
            acc.x = fmaf(v, fa.x, acc.x);
            acc.y = fmaf(v, fa.y, acc.y);
            acc.z = fmaf(v, fb.x, acc.z);
            acc.w = fmaf(v, fb.y, acc.w);
        }
    }

    acc.x = fmaxf(acc.x, 0.f);
    acc.y = fmaxf(acc.y, 0.f);
    acc.z = fmaxf(acc.z, 0.f);
    acc.w = fmaxf(acc.w, 0.f);
    *reinterpret_cast<float4*>(out + (size_t)warp * DIM + lane * 4) = acc;
}

extern "C" void kernel_launch(void* const* d_in, const int* in_sizes, int n_in,
                              void* d_out, int out_size) {
    const float* X    = (const float*)d_in[0];   // [n_nodes, 128]
    const float* W    = (const float*)d_in[1];   // [128, 128]
    const float* vals = (const float*)d_in[2];   // [E]
    const int*   src  = (const int*)d_in[3];     // [E]
    const int*   dst  = (const int*)d_in[4];     // [E]
    float* out = (float*)d_out;

    int n_nodes = in_sizes[0] / DIM;
    int n_edges = in_sizes[2];
    int nb = (n_nodes + SCAN_BLK - 1) / SCAN_BLK;

    // One-time host resources for graph-forked concurrency (no device memory).
    static cudaStream_t s2 = nullptr;
    static cudaEvent_t evFork = nullptr, evJoin = nullptr;
    if (s2 == nullptr) {
        cudaStreamCreateWithFlags(&s2, cudaStreamNonBlocking);
        cudaEventCreateWithFlags(&evFork, cudaEventDisableTiming);
        cudaEventCreateWithFlags(&evJoin, cudaEventDisableTiming);
    }

    // Fork: GEMM chain on s2 runs concurrently with binning chain on stream 0.
    cudaEventRecord(evFork, 0);
    cudaStreamWaitEvent(s2, evFork, 0);

    // --- GEMM chain (s2): W frag pre-pass + tensor-core GEMM -> g_support ---
    wfrag_kernel<<<8, 256, 0, s2>>>(W);
    gemm_mma_kernel<<<(n_nodes + TILE_M - 1) / TILE_M, 256, 0, s2>>>(X, n_nodes);
    cudaEventRecord(evJoin, s2);

    // --- Binning chain (stream 0) ---
    zero_counts_kernel<<<(n_nodes + 255) / 256, 256>>>(n_nodes);
    hist_kernel<<<2048, 256>>>(dst, n_edges);
    scan1_kernel<<<nb, 256>>>(n_nodes);
    scan2_kernel<<<1, 128>>>(nb);
    scan3_kernel<<<(n_nodes + 255) / 256, 256>>>(n_nodes);
    fill_kernel<<<(n_edges + 255) / 256, 256>>>(vals, src, dst, n_edges);

    // Join: gather needs both g_support and the bins.
    cudaStreamWaitEvent(0, evJoin, 0);

    int blocks = (n_nodes * 32 + 255) / 256;
    gather_kernel<<<blocks, 256>>>(out, n_nodes);
}

// round 11
// speedup vs baseline: 1.5187x; 1.0366x over previous
#include <cuda_runtime.h>
#include <cuda_fp16.h>
#include <cuda_bf16.h>
#include <cstring>
#include <cstdint>

#define DIM 128
#define MAX_NODES 100000
#define MAX_EDGES 1600000
#define SCAN_BLK 1024
#define MAX_SCAN_BLOCKS 128
#define TILE_M 32   // GEMM rows per block

// Static device scratch (no allocs allowed).
__device__ __half g_support[MAX_NODES * DIM];           // 25.6 MB, L2-resident
__device__ int g_count[MAX_NODES];
__device__ int g_offset[MAX_NODES];
__device__ int g_cursor[MAX_NODES];
__device__ int g_blocksums[MAX_SCAN_BLOCKS];
__device__ unsigned long long g_bins[MAX_EDGES];        // (val<<32)|src, 12.8 MB
// W pre-packed in mma B-fragment order: [(wn*8+ks)*32 + lane] -> {h0,h1,h2,h3}.
__device__ uint4 g_WfragHi[8 * 8 * 32];                 // 32KB
__device__ uint4 g_WfragLo[8 * 8 * 32];                 // 32KB

__device__ __forceinline__ uint32_t smem_u32(const void* p) {
    uint32_t a;
    asm("{ .reg .u64 t; cvta.to.shared.u64 t, %1; cvt.u32.u64 %0, t; }"
        : "=r"(a) : "l"(p));
    return a;
}
__device__ __forceinline__ unsigned int pack_half2f(float a, float b) {
    __half2 h = __floats2half2_rn(a, b);
    unsigned int u;
    memcpy(&u, &h, 4);
    return u;
}
__device__ __forceinline__ unsigned int pack_bf2(__nv_bfloat16 a, __nv_bfloat16 b) {
    __nv_bfloat162 h;
    h.x = a; h.y = b;
    unsigned int u;
    memcpy(&u, &h, 4);
    return u;
}
__device__ __forceinline__ void ldsm_x4(uint32_t& r0, uint32_t& r1,
                                        uint32_t& r2, uint32_t& r3, uint32_t addr) {
    asm volatile("ldmatrix.sync.aligned.m8n8.x4.shared.b16 {%0,%1,%2,%3}, [%4];"
                 : "=r"(r0), "=r"(r1), "=r"(r2), "=r"(r3) : "r"(addr));
}
__device__ __forceinline__ void mma_bf16(float* c, const uint32_t* a,
                                         uint32_t b0, uint32_t b1) {
    asm volatile("mma.sync.aligned.m16n8k16.row.col.f32.bf16.bf16.f32 "
                 "{%0,%1,%2,%3}, {%4,%5,%6,%7}, {%8,%9}, {%0,%1,%2,%3};"
                 : "+f"(c[0]), "+f"(c[1]), "+f"(c[2]), "+f"(c[3])
                 : "r"(a[0]), "r"(a[1]), "r"(a[2]), "r"(a[3]), "r"(b0), "r"(b1));
}

// XOR-swizzled byte offset for a [rows][128 bf16] tile (256B rows, 16B chunks).
__device__ __forceinline__ uint32_t swz(int row, int chunk) {
    return (uint32_t)(row * 256 + ((chunk ^ (row & 7)) << 4));
}

// ---------------------------------------------------------------------------
// W fragment pre-pass (validated R9): B-fragment order, bf16 hi/lo split.
// ---------------------------------------------------------------------------
__global__ void wfrag_kernel(const float* __restrict__ W) {
    int idx = blockIdx.x * blockDim.x + threadIdx.x;   // 0..2047
    if (idx >= 8 * 8 * 32) return;
    int lane = idx & 31;
    int ks = (idx >> 5) & 7;
    int wn = idx >> 8;
    int m = lane & 3;
    int r = lane >> 2;
    int k0 = ks * 16 + 2 * m;
    int n0 = wn * 16 + r;

    uint4 hi, lo;
    unsigned int* hp = reinterpret_cast<unsigned int*>(&hi);
    unsigned int* lp = reinterpret_cast<unsigned int*>(&lo);
#pragma unroll
    for (int f = 0; f < 4; f++) {
        int n = n0 + ((f >> 1) << 3);
        int k = k0 + ((f & 1) << 3);
        float w0 = W[k * DIM + n];
        float w1 = W[(k + 1) * DIM + n];
        __nv_bfloat16 h0 = __float2bfloat16(w0);
        __nv_bfloat16 h1 = __float2bfloat16(w1);
        __nv_bfloat16 l0 = __float2bfloat16(w0 - __bfloat162float(h0));
        __nv_bfloat16 l1 = __float2bfloat16(w1 - __bfloat162float(h1));
        hp[f] = pack_bf2(h0, h1);
        lp[f] = pack_bf2(l0, l1);
    }
    g_WfragHi[idx] = hi;
    g_WfragLo[idx] = lo;
}

// ---------------------------------------------------------------------------
// Tensor-core GEMM (validated R9) + forced 4 blocks/SM (regs <= 64).
// ---------------------------------------------------------------------------
__global__ void __launch_bounds__(256, 4) gemm_mma_kernel(const float* __restrict__ X,
                                                          int n_rows) {
    __shared__ char sAhi[TILE_M * 256];
    __shared__ char sAlo[TILE_M * 256];

    int tid = threadIdx.x;
    int warp = tid >> 5;
    int lane = tid & 31;
    int row0 = blockIdx.x * TILE_M;

    for (int i = tid; i < TILE_M * 32; i += 256) {
        int r = i >> 5;
        int k4 = i & 31;
        float4 v = make_float4(0.f, 0.f, 0.f, 0.f);
        if (row0 + r < n_rows)
            v = *reinterpret_cast<const float4*>(X + (size_t)(row0 + r) * DIM + k4 * 4);
        const float* vp = reinterpret_cast<const float*>(&v);
        __nv_bfloat16 h[4], l[4];
#pragma unroll
        for (int j = 0; j < 4; j++) {
            h[j] = __float2bfloat16(vp[j]);
            l[j] = __float2bfloat16(vp[j] - __bfloat162float(h[j]));
        }
        uint2 ph, pl;
        memcpy(&ph, h, 8);
        memcpy(&pl, l, 8);
        uint32_t off = swz(r, k4 >> 1) + (k4 & 1) * 8;
        *reinterpret_cast<uint2*>(sAhi + off) = ph;
        *reinterpret_cast<uint2*>(sAlo + off) = pl;
    }
    __syncthreads();

    float acc[2][2][4];
#pragma unroll
    for (int mt = 0; mt < 2; mt++)
#pragma unroll
        for (int nt = 0; nt < 2; nt++)
#pragma unroll
            for (int q = 0; q < 4; q++) acc[mt][nt][q] = 0.f;

    uint32_t aHi = smem_u32(sAhi), aLo = smem_u32(sAlo);

    int a_r = lane & 15;
    int a_c = lane >> 4;

#pragma unroll
    for (int ks = 0; ks < 8; ks++) {
        int c0 = ks * 2;

        uint4 bh = __ldg(&g_WfragHi[(warp * 8 + ks) * 32 + lane]);
        uint4 bl = __ldg(&g_WfragLo[(warp * 8 + ks) * 32 + lane]);

        uint32_t ahi[2][4], alo[2][4];
#pragma unroll
        for (int mt = 0; mt < 2; mt++) {
            int rl = mt * 16 + a_r;
            uint32_t off = swz(rl, c0 + a_c);
            ldsm_x4(ahi[mt][0], ahi[mt][1], ahi[mt][2], ahi[mt][3], aHi + off);
            ldsm_x4(alo[mt][0], alo[mt][1], alo[mt][2], alo[mt][3], aLo + off);
        }

#pragma unroll
        for (int mt = 0; mt < 2; mt++) {
            mma_bf16(acc[mt][0], ahi[mt], bh.x, bh.y);
            mma_bf16(acc[mt][0], ahi[mt], bl.x, bl.y);
            mma_bf16(acc[mt][0], alo[mt], bh.x, bh.y);
            mma_bf16(acc[mt][1], ahi[mt], bh.z, bh.w);
            mma_bf16(acc[mt][1], ahi[mt], bl.z, bl.w);
            mma_bf16(acc[mt][1], alo[mt], bh.z, bh.w);
        }
    }

    int ncol = warp * 16;
#pragma unroll
    for (int mt = 0; mt < 2; mt++) {
        int r0g = row0 + mt * 16 + (lane >> 2);
        int r1g = r0g + 8;
#pragma unroll
        for (int nt = 0; nt < 2; nt++) {
            int col = ncol + nt * 8 + (lane & 3) * 2;
            if (r0g < n_rows)
                *reinterpret_cast<unsigned int*>(g_support + (size_t)r0g * DIM + col) =
                    pack_half2f(acc[mt][nt][0], acc[mt][nt][1]);
            if (r1g < n_rows)
                *reinterpret_cast<unsigned int*>(g_support + (size_t)r1g * DIM + col) =
                    pack_half2f(acc[mt][nt][2], acc[mt][nt][3]);
        }
    }
}

// ---------------------------------------------------------------------------
// CSR binning: zero counts -> histogram -> 3-phase exclusive scan -> fill.
// hist/fill vectorized 4-wide for MLP.
// ---------------------------------------------------------------------------
__global__ void zero_counts_kernel(int n_nodes) {
    int i = blockIdx.x * blockDim.x + threadIdx.x;
    if (i < n_nodes) g_count[i] = 0;
}

__global__ void hist_kernel(const int* __restrict__ dst, int n_edges) {
    int i = blockIdx.x * blockDim.x + threadIdx.x;
    int stride = gridDim.x * blockDim.x;
    int n4 = n_edges >> 2;
    for (int j = i; j < n4; j += stride) {
        int4 d = __ldg(reinterpret_cast<const int4*>(dst) + j);
        atomicAdd(&g_count[d.x], 1);
        atomicAdd(&g_count[d.y], 1);
        atomicAdd(&g_count[d.z], 1);
        atomicAdd(&g_count[d.w], 1);
    }
    for (int j = n4 * 4 + i; j < n_edges; j += stride)
        atomicAdd(&g_count[dst[j]], 1);
}

__global__ void __launch_bounds__(256) scan1_kernel(int n_nodes) {
    __shared__ int s[256];
    int base = blockIdx.x * SCAN_BLK;
    int t = threadIdx.x;
    int v[4];
    int sum = 0;
#pragma unroll
    for (int j = 0; j < 4; j++) {
        int idx = base + t * 4 + j;
        v[j] = (idx < n_nodes) ? g_count[idx] : 0;
        sum += v[j];
    }
    s[t] = sum;
    __syncthreads();
    for (int off = 1; off < 256; off <<= 1) {
        int x = (t >= off) ? s[t - off] : 0;
        __syncthreads();
        s[t] += x;
        __syncthreads();
    }
    int excl = s[t] - sum;
    if (t == 255) g_blocksums[blockIdx.x] = s[255];
    int run = excl;
#pragma unroll
    for (int j = 0; j < 4; j++) {
        int idx = base + t * 4 + j;
        if (idx < n_nodes) g_offset[idx] = run;
        run += v[j];
    }
}

__global__ void __launch_bounds__(128) scan2_kernel(int nb) {
    __shared__ int s[128];
    int t = threadIdx.x;
    int v = (t < nb) ? g_blocksums[t] : 0;
    s[t] = v;
    __syncthreads();
    for (int off = 1; off < 128; off <<= 1) {
        int x = (t >= off) ? s[t - off] : 0;
        __syncthreads();
        s[t] += x;
        __syncthreads();
    }
    if (t < nb) g_blocksums[t] = s[t] - v;
}

__global__ void scan3_kernel(int n_nodes) {
    int i = blockIdx.x * blockDim.x + threadIdx.x;
    if (i < n_nodes) {
        int o = g_offset[i] + g_blocksums[i / SCAN_BLK];
        g_offset[i] = o;
        g_cursor[i] = o;
    }
}

__global__ void fill_kernel(const float* __restrict__ vals,
                            const int* __restrict__ src,
                            const int* __restrict__ dst,
                            int n_edges) {
    int i = blockIdx.x * blockDim.x + threadIdx.x;
    int stride = gridDim.x * blockDim.x;
    int n4 = n_edges >> 2;
    for (int j = i; j < n4; j += stride) {
        float4 v = __ldg(reinterpret_cast<const float4*>(vals) + j);
        int4 s = __ldg(reinterpret_cast<const int4*>(src) + j);
        int4 d = __ldg(reinterpret_cast<const int4*>(dst) + j);
        const float* vp = reinterpret_cast<const float*>(&v);
        const int* sp = reinterpret_cast<const int*>(&s);
        const int* dp = reinterpret_cast<const int*>(&d);
#pragma unroll
        for (int q = 0; q < 4; q++) {
            int pos = atomicAdd(&g_cursor[dp[q]], 1);
            g_bins[pos] = ((unsigned long long)__float_as_uint(vp[q]) << 32) |
                          (unsigned int)sp[q];
        }
    }
    for (int j = n4 * 4 + i; j < n_edges; j += stride) {
        int pos = atomicAdd(&g_cursor[dst[j]], 1);
        g_bins[pos] = ((unsigned long long)__float_as_uint(vals[j]) << 32) |
                      (unsigned int)src[j];
    }
}

// ---------------------------------------------------------------------------
// Gather: one warp per dst node, 8-edge pipeline (deg~16 -> 2 rounds),
// fused ReLU, single write per node.
// ---------------------------------------------------------------------------
__global__ void __launch_bounds__(256) gather_kernel(float* __restrict__ out,
                                                     int n_nodes) {
    int warp = (blockIdx.x * blockDim.x + threadIdx.x) >> 5;
    int lane = threadIdx.x & 31;
    if (warp >= n_nodes) return;

    int o0 = g_offset[warp];
    int deg = g_count[warp];

    float4 acc = make_float4(0.f, 0.f, 0.f, 0.f);

    for (int e = 0; e < deg; e += 8) {
        unsigned long long p[8];
#pragma unroll
        for (int j = 0; j < 8; j++)
            p[j] = (e + j < deg) ? __ldg(g_bins + o0 + e + j) : 0ull;

        uint2 hv[8];
#pragma unroll
        for (int j = 0; j < 8; j++) {
            int s = (int)(p[j] & 0xffffffffull);
            hv[j] = __ldg(reinterpret_cast<const uint2*>(
                g_support + (size_t)s * DIM + lane * 4));
        }
#pragma unroll
        for (int j = 0; j < 8; j++) {
            float v = __uint_as_float((unsigned int)(p[j] >> 32));
            __half2 a, b;
            memcpy(&a, &hv[j].x, 4);
            memcpy(&b, &hv[j].y, 4);
            float2 fa = __half22float2(a);
            float2 fb = __half22float2(b);
            acc.x = fmaf(v, fa.x, acc.x);
            acc.y = fmaf(v, fa.y, acc.y);
            acc.z = fmaf(v, fb.x, acc.z);
            acc.w = fmaf(v, fb.y, acc.w);
        }
    }

    acc.x = fmaxf(acc.x, 0.f);
    acc.y = fmaxf(acc.y, 0.f);
    acc.z = fmaxf(acc.z, 0.f);
    acc.w = fmaxf(acc.w, 0.f);
    *reinterpret_cast<float4*>(out + (size_t)warp * DIM + lane * 4) = acc;
}

extern "C" void kernel_launch(void* const* d_in, const int* in_sizes, int n_in,
                              void* d_out, int out_size) {
    const float* X    = (const float*)d_in[0];   // [n_nodes, 128]
    const float* W    = (const float*)d_in[1];   // [128, 128]
    const float* vals = (const float*)d_in[2];   // [E]
    const int*   src  = (const int*)d_in[3];     // [E]
    const int*   dst  = (const int*)d_in[4];     // [E]
    float* out = (float*)d_out;

    int n_nodes = in_sizes[0] / DIM;
    int n_edges = in_sizes[2];
    int nb = (n_nodes + SCAN_BLK - 1) / SCAN_BLK;

    // One-time host resources for graph-forked concurrency (no device memory).
    static cudaStream_t s2 = nullptr;
    static cudaEvent_t evFork = nullptr, evJoin = nullptr;
    if (s2 == nullptr) {
        cudaStreamCreateWithFlags(&s2, cudaStreamNonBlocking);
        cudaEventCreateWithFlags(&evFork, cudaEventDisableTiming);
        cudaEventCreateWithFlags(&evJoin, cudaEventDisableTiming);
    }

    // Fork: GEMM chain on s2 runs concurrently with binning chain on stream 0.
    cudaEventRecord(evFork, 0);
    cudaStreamWaitEvent(s2, evFork, 0);

    // --- GEMM chain (s2): W frag pre-pass + tensor-core GEMM -> g_support ---
    wfrag_kernel<<<8, 256, 0, s2>>>(W);
    gemm_mma_kernel<<<(n_nodes + TILE_M - 1) / TILE_M, 256, 0, s2>>>(X, n_nodes);
    cudaEventRecord(evJoin, s2);

    // --- Binning chain (stream 0) ---
    zero_counts_kernel<<<(n_nodes + 255) / 256, 256>>>(n_nodes);
    hist_kernel<<<1024, 256>>>(dst, n_edges);
    scan1_kernel<<<nb, 256>>>(n_nodes);
    scan2_kernel<<<1, 128>>>(nb);
    scan3_kernel<<<(n_nodes + 255) / 256, 256>>>(n_nodes);
    fill_kernel<<<1024, 256>>>(vals, src, dst, n_edges);

    // Join: gather needs both g_support and the bins.
    cudaStreamWaitEvent(0, evJoin, 0);

    int blocks = (n_nodes * 32 + 255) / 256;
    gather_kernel<<<blocks, 256>>>(out, n_nodes);
}